// round 7
// baseline (speedup 1.0000x reference)
#include <cuda_runtime.h>
#include <math.h>

// Problem constants (B=64, T=500, C=40)
#define CC   40
#define CP1  41          // gmem row stride of y_pred last dim
#define RS   44          // smem row stride (16B-aligned rows, conflict-free LDS.128)
#define NB   8           // Cholesky block size
#define WPB  4           // warps (matrices) per block
#define PTS  40          // transposed-panel row stride (16B-aligned tiles)
#define MATG (CC*CP1)    // 1640 floats per matrix in gmem
#define FULLM 0xFFFFFFFFu

__device__ double g_part[8192];   // per-block partial sums (overwritten every launch)

__global__ void __launch_bounds__(WPB*32)
nll_kernel(const float* __restrict__ yt, const float* __restrict__ yp, int nmat)
{
    // per warp: matrix 40*44 + rhs 40 + transposed panel 8*40 = 2120 floats
    __shared__ float  smem[WPB][CC*RS + CC + NB*PTS];
    __shared__ double wacc[WPB];

    const int lane = threadIdx.x & 31;
    const int warp = threadIdx.x >> 5;
    const int m    = blockIdx.x * WPB + warp;

    float acc = 0.0f;

    float* s  = smem[warp];
    float* r  = s + CC*RS;
    float* pt = r + CC;          // Pt[k][row] : transposed current panel

    if (m < nmat) {
        // ---- load sigma+mu (linear, coalesced float4) into stride-44 smem ----
        const float4* gp = (const float4*)(yp + (size_t)m * MATG);
        for (int v = lane; v < MATG/4; v += 32) {
            float4 q = gp[v];
            int e = v << 2;
            int i = e / CP1;            // magic-multiply division
            int j = e - i * CP1;
            float* p = s + i*RS + j;
            // elements may wrap to next row once; wrapped offset = +RS-CP1 = +3
            p[0] = q.x;
            p[(j+1 >= CP1) ? 4 : 1] = q.y;
            p[(j+2 >= CP1) ? 5 : 2] = q.z;
            p[(j+3 >= CP1) ? 6 : 3] = q.w;
        }
        __syncwarp();

        // ---- rhs: diff = y_true - mu (mu is column 40) ----
        const float* ytm = yt + (size_t)m * CC;
        for (int i = lane; i < CC; i += 32)
            r[i] = ytm[i] - s[i*RS + CC];
        __syncwarp();

        float quad2 = 0.f;          // sum z^2
        float logsum = 0.f;         // sum log(diag)  (= 2 * logdet_half)

        // ---- blocked Cholesky, register-resident panel, fused forward solve ----
        #pragma unroll
        for (int kb = 0; kb < CC; kb += NB) {
            const bool own  = lane < (CC - kb);               // lane owns row kb+lane
            const bool own2 = (kb == 0) && (lane < CC - 32);  // extra rows 32..39

            float a[NB] = {0,0,0,0,0,0,0,0};
            float b[NB] = {0,0,0,0,0,0,0,0};
            float rr = 0.f, rr2 = 0.f;

            if (own) {
                const float4* ap = (const float4*)(s + (kb + lane)*RS + kb);
                float4 A0 = ap[0], A1 = ap[1];
                a[0]=A0.x; a[1]=A0.y; a[2]=A0.z; a[3]=A0.w;
                a[4]=A1.x; a[5]=A1.y; a[6]=A1.z; a[7]=A1.w;
                rr = r[kb + lane];
            }
            if (own2) {
                const float4* bp = (const float4*)(s + (32 + lane)*RS);
                float4 B0 = bp[0], B1 = bp[1];
                b[0]=B0.x; b[1]=B0.y; b[2]=B0.z; b[3]=B0.w;
                b[4]=B1.x; b[5]=B1.y; b[6]=B1.z; b[7]=B1.w;
                rr2 = r[32 + lane];
            }

            float dp = 1.0f;   // product of 8 panel diagonals

            // 8 factorization steps, branchless: cells above the diagonal and
            // already-solved rhs entries get harmlessly corrupted (never read).
            #pragma unroll
            for (int t = 0; t < NB; t++) {
                float diag = __shfl_sync(FULLM, a[t], t);   // lane t holds true diag
                float inv  = rsqrtf(diag);                  // single MUFU
                dp        *= diag;
                float zk   = __shfl_sync(FULLM, rr, t) * inv;
                quad2      = fmaf(zk, zk, quad2);

                float lit = a[t] * inv;
                float cv[NB];
                #pragma unroll
                for (int j = t + 1; j < NB; j++)
                    cv[j] = __shfl_sync(FULLM, lit, j);     // L[kb+j][k]

                // uniform update (lane==t naturally stores ~sqrt(diag))
                a[t] = lit;
                #pragma unroll
                for (int j = t + 1; j < NB; j++)
                    a[j] = fmaf(-lit, cv[j], a[j]);
                rr = fmaf(-lit, zk, rr);

                if (own2) {                       // rows 32..39 (kb==0 only)
                    float l2 = b[t] * inv;
                    b[t] = l2;
                    #pragma unroll
                    for (int j = t + 1; j < NB; j++)
                        b[j] = fmaf(-l2, cv[j], b[j]);
                    rr2 = fmaf(-l2, zk, rr2);
                }
            }
            logsum += __logf(dp);   // one log per panel (dp bounded, fp32-safe)

            // write panel back TRANSPOSED (Pt[k][row]) + rhs. The square copy
            // of L in s is never consumed, so no row-wise writeback needed.
            if (own) {
                #pragma unroll
                for (int k = 0; k < NB; k++)
                    pt[k*PTS + kb + lane] = a[k];
                r[kb + lane] = rr;
            }
            if (own2) {
                #pragma unroll
                for (int k = 0; k < NB; k++)
                    pt[k*PTS + 32 + lane] = b[k];
                r[32 + lane] = rr2;
            }
            __syncwarp();

            // --- trailing rank-8 update: packed f32x2 FMA, rectangular ---
            // Uniform jb bound: cells with j>i are garbage but provably never
            // consumed (stay inside the padded row).
            if (kb + NB < CC) {
                const int i = kb + NB + lane;           // one row per lane
                if (i < CC) {
                    // this row's 8 negated multipliers, duplicated into f32x2
                    unsigned long long an[NB];
                    #pragma unroll
                    for (int k = 0; k < NB; k++) {
                        float nv = -pt[k*PTS + i];
                        asm("mov.b64 %0, {%1, %1};" : "=l"(an[k]) : "f"(nv));
                    }
                    #pragma unroll
                    for (int jb = kb + NB; jb <= 36; jb += 4) {
                        double2 cd = *(const double2*)(s + i*RS + jb);
                        unsigned long long c01 = __double_as_longlong(cd.x);
                        unsigned long long c23 = __double_as_longlong(cd.y);
                        #pragma unroll
                        for (int k = 0; k < NB; k++) {
                            // broadcast: all lanes read Pt[k][jb..jb+3]
                            double2 bd = *(const double2*)(pt + k*PTS + jb);
                            asm("fma.rn.f32x2 %0, %1, %2, %0;"
                                : "+l"(c01)
                                : "l"(an[k]), "l"(__double_as_longlong(bd.x)));
                            asm("fma.rn.f32x2 %0, %1, %2, %0;"
                                : "+l"(c23)
                                : "l"(an[k]), "l"(__double_as_longlong(bd.y)));
                        }
                        double2 od;
                        od.x = __longlong_as_double(c01);
                        od.y = __longlong_as_double(c23);
                        *(double2*)(s + i*RS + jb) = od;
                    }
                }
                __syncwarp();
            }
        }
        acc = 0.5f*quad2 + 0.5f*logsum;   // identical on every lane
    }

    // ---- block reduction, one partial per block (no atomics) ----
    if (lane == 0) wacc[warp] = (double)acc;
    __syncthreads();
    if (threadIdx.x == 0 && blockIdx.x < 8192) {
        double tsum = 0.0;
        #pragma unroll
        for (int w = 0; w < WPB; w++) tsum += wacc[w];
        g_part[blockIdx.x] = tsum;
    }
}

__global__ void __launch_bounds__(1024)
fin_kernel(float* out, int nblocks)
{
    __shared__ double red[32];
    double ssum = 0.0;
    for (int i = threadIdx.x; i < nblocks; i += 1024) ssum += g_part[i];
    #pragma unroll
    for (int off = 16; off > 0; off >>= 1)
        ssum += __shfl_down_sync(FULLM, ssum, off);
    if ((threadIdx.x & 31) == 0) red[threadIdx.x >> 5] = ssum;
    __syncthreads();
    if (threadIdx.x < 32) {
        double t = (threadIdx.x < 32) ? red[threadIdx.x] : 0.0;
        #pragma unroll
        for (int off = 16; off > 0; off >>= 1)
            t += __shfl_down_sync(FULLM, t, off);
        if (threadIdx.x == 0) {
            // result = sum(0.5*quad + logdet_half)/B + T*(C/2)*log(2*pi)
            const double LOG2PI = 1.8378770664093453;
            out[0] = (float)(t / 64.0 + 500.0 * 20.0 * LOG2PI);
        }
    }
}

extern "C" void kernel_launch(void* const* d_in, const int* in_sizes, int n_in,
                              void* d_out, int out_size)
{
    // identify inputs by size (y_true is the small one)
    int i_yt = 0, i_yp = 1;
    if (n_in >= 2 && in_sizes[0] > in_sizes[1]) { i_yt = 1; i_yp = 0; }
    const float* yt = (const float*)d_in[i_yt];
    const float* yp = (const float*)d_in[i_yp];
    int nmat = in_sizes[i_yt] / CC;           // 32000

    int blocks = (nmat + WPB - 1) / WPB;      // 8000 (fits g_part[8192])
    if (blocks > 8192) blocks = 8192;
    nll_kernel<<<blocks, WPB*32>>>(yt, yp, nmat);
    fin_kernel<<<1, 1024>>>((float*)d_out, blocks);
}

// round 9
// speedup vs baseline: 1.0566x; 1.0566x over previous
#include <cuda_runtime.h>
#include <math.h>

// Problem constants (B=64, T=500, C=40)
#define CC   40
#define CP1  41          // gmem row stride of y_pred last dim
#define RS   44          // smem row stride (16B-aligned rows, conflict-free LDS.128)
#define NB   8           // Cholesky block size
#define WPB  4           // warps (matrices) per block
#define MATG (CC*CP1)    // 1640 floats per matrix in gmem
#define FULLM 0xFFFFFFFFu
#define IDX(t,j) ((t)*((t)+1)/2 + (j))   // packed lower-triangle index, j<=t

__device__ double g_part[8192];   // per-block partial sums (overwritten every launch)

__global__ void __launch_bounds__(WPB*32)
nll_kernel(const float* __restrict__ yt, const float* __restrict__ yp, int nmat)
{
    // per warp: matrix 40*44 = 1760 floats + rhs 40 floats
    __shared__ float  smem[WPB][CC*RS + CC];
    __shared__ double wacc[WPB];

    const int lane = threadIdx.x & 31;
    const int warp = threadIdx.x >> 5;
    const int m    = blockIdx.x * WPB + warp;

    float acc = 0.0f;

    float* s = smem[warp];
    float* r = s + CC*RS;

    if (m < nmat) {
        // ---- load sigma+mu (linear, coalesced float4) into stride-44 smem ----
        const float4* gp = (const float4*)(yp + (size_t)m * MATG);
        for (int v = lane; v < MATG/4; v += 32) {
            float4 q = gp[v];
            int e = v << 2;
            int i = e / CP1;            // magic-multiply division
            int j = e - i * CP1;
            float* p = s + i*RS + j;
            // elements may wrap to next row once; wrapped offset = +RS-CP1 = +3
            p[0] = q.x;
            p[(j+1 >= CP1) ? 4 : 1] = q.y;
            p[(j+2 >= CP1) ? 5 : 2] = q.z;
            p[(j+3 >= CP1) ? 6 : 3] = q.w;
        }
        __syncwarp();

        // ---- rhs: diff = y_true - mu (mu is column 40) ----
        const float* ytm = yt + (size_t)m * CC;
        for (int i = lane; i < CC; i += 32)
            r[i] = ytm[i] - s[i*RS + CC];
        __syncwarp();

        float quad2 = 0.f;          // sum z^2  (redundant, same on all lanes)
        float logsum = 0.f;         // sum log(diag)

        // ---- blocked Cholesky: shuffle-free, redundant 8x8 block factor ----
        #pragma unroll
        for (int kb = 0; kb < CC; kb += NB) {

            // --- every lane loads the 8x8 diagonal block (broadcast LDS) ---
            float Lb[36];
            #pragma unroll
            for (int t = 0; t < NB; t++)
                #pragma unroll
                for (int j = 0; j <= t; j++)
                    Lb[IDX(t,j)] = s[(kb + t)*RS + kb + j];

            // --- redundant in-register 8x8 Cholesky ---
            float inv[NB];
            float dp = 1.0f;
            #pragma unroll
            for (int t = 0; t < NB; t++) {
                float diag = Lb[IDX(t,t)];
                float iv   = rsqrtf(diag);      // single MUFU per step
                inv[t] = iv;
                dp    *= diag;
                #pragma unroll
                for (int j = t + 1; j < NB; j++)
                    Lb[IDX(j,t)] *= iv;
                #pragma unroll
                for (int j = t + 1; j < NB; j++)
                    #pragma unroll
                    for (int k = t + 1; k <= j; k++)
                        Lb[IDX(j,k)] = fmaf(-Lb[IDX(j,t)], Lb[IDX(k,t)], Lb[IDX(j,k)]);
            }
            logsum += __logf(dp);   // one log per panel (dp bounded, fp32-safe)

            // --- redundant forward solve of the 8 block rhs entries ---
            float z[NB];
            #pragma unroll
            for (int t = 0; t < NB; t++) {
                float v = r[kb + t];            // broadcast LDS
                #pragma unroll
                for (int j = 0; j < t; j++)
                    v = fmaf(-Lb[IDX(t,j)], z[j], v);
                v *= inv[t];
                z[t]  = v;
                quad2 = fmaf(v, v, quad2);
            }

            // --- each lane solves its own off-block panel row (no comms) ---
            const int  i   = kb + NB + lane;    // off-block rows kb+8..39
            const bool own = i < CC;            // 32-kb lanes active
            float a[NB];
            if (own) {
                const float4* ap = (const float4*)(s + i*RS + kb);
                float4 A0 = ap[0], A1 = ap[1];
                a[0]=A0.x; a[1]=A0.y; a[2]=A0.z; a[3]=A0.w;
                a[4]=A1.x; a[5]=A1.y; a[6]=A1.z; a[7]=A1.w;
                float rr = r[i];
                #pragma unroll
                for (int t = 0; t < NB; t++) {
                    float v = a[t];
                    #pragma unroll
                    for (int j = 0; j < t; j++)
                        v = fmaf(-Lb[IDX(t,j)], a[j], v);
                    v *= inv[t];
                    a[t] = v;
                    rr = fmaf(-v, z[t], rr);
                }
                // writeback multipliers (consumed by trailing broadcasts) + rhs
                float4* wp = (float4*)(s + i*RS + kb);
                wp[0] = make_float4(a[0],a[1],a[2],a[3]);
                wp[1] = make_float4(a[4],a[5],a[6],a[7]);
                r[i] = rr;
            }
            __syncwarp();

            // --- trailing rank-8 update (R6 form), av reused from registers ---
            // Rectangular jb bound: cells with j>i are garbage but provably
            // never consumed (stay inside the padded row).
            if (kb + NB < CC) {
                if (own) {
                    #pragma unroll
                    for (int jb = kb + NB; jb <= 36; jb += 4) {
                        float4 c = *(const float4*)(s + i*RS + jb);
                        float cvv[4] = {c.x, c.y, c.z, c.w};
                        #pragma unroll
                        for (int q = 0; q < 4; q++) {
                            // broadcast loads: all lanes read row (jb+q)'s panel
                            const float4* bp = (const float4*)(s + (jb + q)*RS + kb);
                            float4 b0 = bp[0], b1 = bp[1];
                            cvv[q] -= a[0]*b0.x + a[1]*b0.y + a[2]*b0.z + a[3]*b0.w
                                    + a[4]*b1.x + a[5]*b1.y + a[6]*b1.z + a[7]*b1.w;
                        }
                        *(float4*)(s + i*RS + jb) = make_float4(cvv[0],cvv[1],cvv[2],cvv[3]);
                    }
                }
                __syncwarp();
            }
        }
        acc = 0.5f*quad2 + 0.5f*logsum;   // identical on every lane
    }

    // ---- block reduction, one partial per block (no atomics) ----
    if (lane == 0) wacc[warp] = (double)acc;
    __syncthreads();
    if (threadIdx.x == 0 && blockIdx.x < 8192) {
        double tsum = 0.0;
        #pragma unroll
        for (int w = 0; w < WPB; w++) tsum += wacc[w];
        g_part[blockIdx.x] = tsum;
    }
}

__global__ void __launch_bounds__(1024)
fin_kernel(float* out, int nblocks)
{
    __shared__ double red[32];
    double ssum = 0.0;
    for (int i = threadIdx.x; i < nblocks; i += 1024) ssum += g_part[i];
    #pragma unroll
    for (int off = 16; off > 0; off >>= 1)
        ssum += __shfl_down_sync(FULLM, ssum, off);
    if ((threadIdx.x & 31) == 0) red[threadIdx.x >> 5] = ssum;
    __syncthreads();
    if (threadIdx.x < 32) {
        double t = red[threadIdx.x];
        #pragma unroll
        for (int off = 16; off > 0; off >>= 1)
            t += __shfl_down_sync(FULLM, t, off);
        if (threadIdx.x == 0) {
            // result = sum(0.5*quad + logdet_half)/B + T*(C/2)*log(2*pi)
            const double LOG2PI = 1.8378770664093453;
            out[0] = (float)(t / 64.0 + 500.0 * 20.0 * LOG2PI);
        }
    }
}

extern "C" void kernel_launch(void* const* d_in, const int* in_sizes, int n_in,
                              void* d_out, int out_size)
{
    // identify inputs by size (y_true is the small one)
    int i_yt = 0, i_yp = 1;
    if (n_in >= 2 && in_sizes[0] > in_sizes[1]) { i_yt = 1; i_yp = 0; }
    const float* yt = (const float*)d_in[i_yt];
    const float* yp = (const float*)d_in[i_yp];
    int nmat = in_sizes[i_yt] / CC;           // 32000

    int blocks = (nmat + WPB - 1) / WPB;      // 8000 (fits g_part[8192])
    if (blocks > 8192) blocks = 8192;
    nll_kernel<<<blocks, WPB*32>>>(yt, yp, nmat);
    fin_kernel<<<1, 1024>>>((float*)d_out, blocks);
}